// round 6
// baseline (speedup 1.0000x reference)
#include <cuda_runtime.h>
#include <cuda_bf16.h>

// NeuSSampler inverse-CDF importance sampling — v5 "mark + max-scan".
// weights [R,128,1] f32, existing_bins [R,129] f32, nears [R,1], fars [R,1]
// -> out [R,65] f32.   One warp per ray. Fully branch-free:
//  A) float4 weight load + warp scan -> 5 CDF values/lane (padding folded).
//  B) stage interleaved (cdf,bin) float2 pairs to smem (2x STS.128/lane).
//  C) segment-start boundaries m_g = floor(65*cdf_g + 0.5); atomicMax-mark
//     mark[m_g] = g  (owner of query j is max{g : m_g <= j}).
//  D) warp inclusive max-scan over the 65 marks -> owner(j) in registers.
//  E) gather: 2x LDS.64 pair fetch + lerp + coalesced STG per output.

#define S_SAMP 128
#define NB 65
#define HIST_PAD 1e-5f
#define EPS_V 1e-5f
#define WARPS_PER_BLOCK 8
#define NTHREADS (WARPS_PER_BLOCK * 32)
#define INV_NB (1.0f / 65.0f)

__global__ __launch_bounds__(NTHREADS)
void neus_sampler_kernel(const float* __restrict__ weights,
                         const float* __restrict__ ebins,
                         const float* __restrict__ nears,
                         const float* __restrict__ fars,
                         float* __restrict__ out,
                         int R)
{
    __shared__ __align__(16) float2 pair_sm[WARPS_PER_BLOCK][130]; // (cdf,bin)
    __shared__ int mark_sm[WARPS_PER_BLOCK][66];

    const int warp = threadIdx.x >> 5;
    const int lane = threadIdx.x & 31;
    const int ray  = blockIdx.x * WARPS_PER_BLOCK + warp;
    if (ray >= R) return;

    int* mk = mark_sm[warp];
    mk[lane]      = 0;
    mk[lane + 32] = 0;
    if (lane == 0) mk[64] = 0;

    // ---- A. raw cumsum + warp scan (512B-stride rows: float4 ok) ----
    const float4 wv = *reinterpret_cast<const float4*>(
        weights + (size_t)ray * S_SAMP + lane * 4);
    const float l0 = wv.x;
    const float l1 = l0 + wv.y;
    const float l2 = l1 + wv.z;
    const float l3 = l2 + wv.w;

    float pre = l3;
    #pragma unroll
    for (int off = 1; off < 32; off <<= 1) {
        float v = __shfl_up_sync(0xffffffffu, pre, off);
        if (lane >= off) pre += v;
    }
    const float total_raw = __shfl_sync(0xffffffffu, pre, 31);
    const float excl      = pre - l3;

    const float total_wp = total_raw + (float)S_SAMP * HIST_PAD;
    const float padding  = fmaxf(0.0f, EPS_V - total_wp);
    const float inv_wsum = __fdividef(1.0f, total_wp + padding);
    const float step     = HIST_PAD + padding * (1.0f / (float)S_SAMP);

    const int k  = lane * 4;
    const float kf = (float)k;
    const float c0 = fmaf(kf,        step, excl     ) * inv_wsum;
    const float c1 = fmaf(kf + 1.0f, step, excl + l0) * inv_wsum;
    const float c2 = fmaf(kf + 2.0f, step, excl + l1) * inv_wsum;
    const float c3 = fmaf(kf + 3.0f, step, excl + l2) * inv_wsum;
    const float c4 = fmaf(kf + 4.0f, step, excl + l3) * inv_wsum;

    // ---- bins (516B row stride -> scalar loads) ----
    const float* eb = ebins + (size_t)ray * (S_SAMP + 1) + k;
    const float b0 = __ldg(eb + 0);
    const float b1 = __ldg(eb + 1);
    const float b2 = __ldg(eb + 2);
    const float b3 = __ldg(eb + 3);

    // ---- B. stage interleaved (cdf,bin) pairs: 2x 16B stores ----
    float4 p01; p01.x = c0; p01.y = b0; p01.z = c1; p01.w = b1;
    float4 p23; p23.x = c2; p23.y = b2; p23.z = c3; p23.w = b3;
    *reinterpret_cast<float4*>(&pair_sm[warp][k])     = p01;
    *reinterpret_cast<float4*>(&pair_sm[warp][k + 2]) = p23;
    if (lane == 31) {
        float2 pl; pl.x = c4; pl.y = __ldg(eb + 4);   // ebins[ray][128]
        pair_sm[warp][128] = pl;
    }

    // ---- C. segment-start boundaries + atomicMax marking ----
    const int m1 = __float2int_rd(fmaf(65.0f, c1, 0.5f));
    const int m2 = __float2int_rd(fmaf(65.0f, c2, 0.5f));
    const int m3 = __float2int_rd(fmaf(65.0f, c3, 0.5f));
    const int m4 = __float2int_rd(fmaf(65.0f, c4, 0.5f));
    int m0 = __shfl_up_sync(0xffffffffu, m4, 1);
    if (lane == 0) m0 = 0;

    __syncwarp();   // mark init visible before atomics
    if (m0 < NB) atomicMax(&mk[m0], k);
    if (m1 < NB) atomicMax(&mk[m1], k + 1);
    if (m2 < NB) atomicMax(&mk[m2], k + 2);
    if (m3 < NB) atomicMax(&mk[m3], k + 3);
    __syncwarp();   // marks complete before scan reads

    // ---- D. inclusive max-scan over 65 marks -> owner(j) in registers ----
    int v0 = mk[lane];
    #pragma unroll
    for (int off = 1; off < 32; off <<= 1) {
        int t = __shfl_up_sync(0xffffffffu, v0, off);
        if (lane >= off) v0 = max(v0, t);
    }
    const int carry0 = __shfl_sync(0xffffffffu, v0, 31);
    int v1 = mk[lane + 32];
    #pragma unroll
    for (int off = 1; off < 32; off <<= 1) {
        int t = __shfl_up_sync(0xffffffffu, v1, off);
        if (lane >= off) v1 = max(v1, t);
    }
    v1 = max(v1, carry0);
    const int v64 = max(mk[64], __shfl_sync(0xffffffffu, v1, 31));

    // ---- E. branch-free gather + coalesced stores ----
    const float nearv = nears[ray];
    const float dfn   = fars[ray] - nearv;
    float* orow = out + (size_t)ray * NB;
    const float2* pw = pair_sm[warp];

    {
        const float u  = ((float)lane + 0.5f) * INV_NB;
        const float2 pa = pw[v0];
        const float2 pb = pw[v0 + 1];
        const float t  = (u - pa.x) * __fdividef(1.0f, pb.x - pa.x);
        const float bb = fmaf(t, pb.y - pa.y, pa.y);
        orow[lane] = fmaf(bb, dfn, nearv);
    }
    {
        const float u  = ((float)(lane + 32) + 0.5f) * INV_NB;
        const float2 pa = pw[v1];
        const float2 pb = pw[v1 + 1];
        const float t  = (u - pa.x) * __fdividef(1.0f, pb.x - pa.x);
        const float bb = fmaf(t, pb.y - pa.y, pa.y);
        orow[lane + 32] = fmaf(bb, dfn, nearv);
    }
    if (lane == 0) {
        const float u  = 64.5f * INV_NB;
        const float2 pa = pw[v64];
        const float2 pb = pw[v64 + 1];
        const float t  = (u - pa.x) * __fdividef(1.0f, pb.x - pa.x);
        const float bb = fmaf(t, pb.y - pa.y, pa.y);
        orow[64] = fmaf(bb, dfn, nearv);
    }
}

extern "C" void kernel_launch(void* const* d_in, const int* in_sizes, int n_in,
                              void* d_out, int out_size) {
    const float* weights = (const float*)d_in[0];
    const float* ebins   = (const float*)d_in[1];
    const float* nears   = (const float*)d_in[2];
    const float* fars    = (const float*)d_in[3];
    float* out = (float*)d_out;

    const int R = in_sizes[2];  // nears has R elements
    const int grid = (R + WARPS_PER_BLOCK - 1) / WARPS_PER_BLOCK;
    neus_sampler_kernel<<<grid, NTHREADS>>>(weights, ebins, nears, fars, out, R);
}

// round 7
// speedup vs baseline: 1.1019x; 1.1019x over previous
#include <cuda_runtime.h>
#include <cuda_bf16.h>

// NeuSSampler inverse-CDF importance sampling — v6 all-register shfl search.
// weights [R,128,1] f32, existing_bins [R,129] f32, nears [R,1], fars [R,1]
// -> out [R,65] f32.  One warp per ray. ZERO shared memory.
//
//  A) float4 weight load + warp scan -> cdf c0..c4 per lane (pad folded).
//  B) bin edges b0..b4 per lane (scalar LDG, 516B row stride).
//  C) per output j: 5-step warp-shuffle binary search over the sorted
//     chunk tops c0_L -> owning lane; 10 shfls fetch owner's (c,b) values;
//     branch-free select of sub-segment; lerp; coalesced store.
//  Rounds: j=lane, j=lane+32, j=64 (uniform search, lane 0 stores).

#define S_SAMP 128
#define NB 65
#define HIST_PAD 1e-5f
#define EPS_V 1e-5f
#define WARPS_PER_BLOCK 8
#define NTHREADS (WARPS_PER_BLOCK * 32)
#define INV_NB (1.0f / 65.0f)
#define FULL 0xffffffffu

__device__ __forceinline__ float query_one(
    float u, float c0, float c1, float c2, float c3, float c4,
    float b0, float b1, float b2, float b3, float b4,
    float dfn, float nearv)
{
    // 5-step ladder over sorted chunk tops c0_L (c0_lane0 == 0 <= u always)
    int pos = 0;
    float cv;
    cv = __shfl_sync(FULL, c0, 16);      if (cv <= u) pos = 16;
    cv = __shfl_sync(FULL, c0, pos + 8); if (cv <= u) pos += 8;
    cv = __shfl_sync(FULL, c0, pos + 4); if (cv <= u) pos += 4;
    cv = __shfl_sync(FULL, c0, pos + 2); if (cv <= u) pos += 2;
    cv = __shfl_sync(FULL, c0, pos + 1); if (cv <= u) pos += 1;

    // fetch owner's cdf + bin values
    const float C0 = __shfl_sync(FULL, c0, pos);
    const float C1 = __shfl_sync(FULL, c1, pos);
    const float C2 = __shfl_sync(FULL, c2, pos);
    const float C3 = __shfl_sync(FULL, c3, pos);
    const float C4 = __shfl_sync(FULL, c4, pos);
    const float B0 = __shfl_sync(FULL, b0, pos);
    const float B1 = __shfl_sync(FULL, b1, pos);
    const float B2 = __shfl_sync(FULL, b2, pos);
    const float B3 = __shfl_sync(FULL, b3, pos);
    const float B4 = __shfl_sync(FULL, b4, pos);

    // largest i in {0..3} with Ci <= u (C0 <= u guaranteed by ladder)
    const bool g1 = (C1 <= u);
    const bool g2 = (C2 <= u);
    const bool g3 = (C3 <= u);

    float clo = C0, chi = C1, blo = B0, bhi = B1;
    if (g1) { clo = C1; chi = C2; blo = B1; bhi = B2; }
    if (g2) { clo = C2; chi = C3; blo = B2; bhi = B3; }
    if (g3) { clo = C3; chi = C4; blo = B3; bhi = B4; }

    const float t  = (u - clo) * __fdividef(1.0f, chi - clo);
    const float bb = fmaf(t, bhi - blo, blo);
    return fmaf(bb, dfn, nearv);
}

__global__ __launch_bounds__(NTHREADS)
void neus_sampler_kernel(const float* __restrict__ weights,
                         const float* __restrict__ ebins,
                         const float* __restrict__ nears,
                         const float* __restrict__ fars,
                         float* __restrict__ out,
                         int R)
{
    const int warp = threadIdx.x >> 5;
    const int lane = threadIdx.x & 31;
    const int ray  = blockIdx.x * WARPS_PER_BLOCK + warp;
    if (ray >= R) return;

    // ---- A. raw cumsum + warp scan (512B-stride rows: float4 ok) ----
    const float4 wv = *reinterpret_cast<const float4*>(
        weights + (size_t)ray * S_SAMP + lane * 4);
    const float l0 = wv.x;
    const float l1 = l0 + wv.y;
    const float l2 = l1 + wv.z;
    const float l3 = l2 + wv.w;

    float pre = l3;
    #pragma unroll
    for (int off = 1; off < 32; off <<= 1) {
        float v = __shfl_up_sync(FULL, pre, off);
        if (lane >= off) pre += v;
    }
    const float total_raw = __shfl_sync(FULL, pre, 31);
    const float excl      = pre - l3;

    const float total_wp = total_raw + (float)S_SAMP * HIST_PAD;
    const float padding  = fmaxf(0.0f, EPS_V - total_wp);
    const float inv_wsum = __fdividef(1.0f, total_wp + padding);
    const float step     = HIST_PAD + padding * (1.0f / (float)S_SAMP);

    const int k  = lane * 4;
    const float kf = (float)k;
    const float c0 = fmaf(kf,        step, excl     ) * inv_wsum;
    const float c1 = fmaf(kf + 1.0f, step, excl + l0) * inv_wsum;
    const float c2 = fmaf(kf + 2.0f, step, excl + l1) * inv_wsum;
    const float c3 = fmaf(kf + 3.0f, step, excl + l2) * inv_wsum;
    const float c4 = fmaf(kf + 4.0f, step, excl + l3) * inv_wsum;

    // ---- B. bin edges (516B row stride -> scalar loads) ----
    const float* eb = ebins + (size_t)ray * (S_SAMP + 1) + k;
    const float b0 = __ldg(eb + 0);
    const float b1 = __ldg(eb + 1);
    const float b2 = __ldg(eb + 2);
    const float b3 = __ldg(eb + 3);
    float b4 = __shfl_down_sync(FULL, b0, 1);
    if (lane == 31) b4 = __ldg(eb + 4);   // ebins[ray][128]

    const float nearv = nears[ray];
    const float dfn   = fars[ray] - nearv;
    float* orow = out + (size_t)ray * NB;

    // ---- C. three gather rounds, all-register search ----
    const float u0 = ((float)lane + 0.5f) * INV_NB;
    const float r0 = query_one(u0, c0, c1, c2, c3, c4,
                               b0, b1, b2, b3, b4, dfn, nearv);
    orow[lane] = r0;

    const float u1 = ((float)(lane + 32) + 0.5f) * INV_NB;
    const float r1 = query_one(u1, c0, c1, c2, c3, c4,
                               b0, b1, b2, b3, b4, dfn, nearv);
    orow[lane + 32] = r1;

    const float u2 = 64.5f * INV_NB;                 // uniform across warp
    const float r2 = query_one(u2, c0, c1, c2, c3, c4,
                               b0, b1, b2, b3, b4, dfn, nearv);
    if (lane == 0) orow[64] = r2;
}

extern "C" void kernel_launch(void* const* d_in, const int* in_sizes, int n_in,
                              void* d_out, int out_size) {
    const float* weights = (const float*)d_in[0];
    const float* ebins   = (const float*)d_in[1];
    const float* nears   = (const float*)d_in[2];
    const float* fars    = (const float*)d_in[3];
    float* out = (float*)d_out;

    const int R = in_sizes[2];  // nears has R elements
    const int grid = (R + WARPS_PER_BLOCK - 1) / WARPS_PER_BLOCK;
    neus_sampler_kernel<<<grid, NTHREADS>>>(weights, ebins, nears, fars, out, R);
}